// round 5
// baseline (speedup 1.0000x reference)
#include <cuda_runtime.h>
#include <math.h>
#include <stdint.h>

#define NTOK 8192
#define DIM  1024
#define NEXP 32
#define HID  128
#define TK   4
#define SHID 512
#define NROWS (NTOK*TK)

// ---------------- scratch (device globals; no allocations) ----------------
__device__ __align__(16) float g_logits[NTOK * NEXP];
__device__ __align__(16) int   g_topk_idx[NROWS];
__device__ __align__(16) float g_topk_sc[NROWS];
__device__ __align__(16) int   g_counts[NEXP];
__device__ __align__(16) int   g_offsets[NEXP + 1];
__device__ __align__(16) int   g_cursor[NEXP];
__device__ __align__(16) int   g_bucket_tok[NROWS];
__device__ __align__(16) float g_bucket_sc[NROWS];
__device__ __align__(16) int   g_tok_pos[NROWS];
// tf32-bit, k-permuted copies (pre-convert pass)
__device__ __align__(16) float g_xt[(size_t)NTOK * DIM];
__device__ __align__(16) float g_gwt[(size_t)NEXP * HID * DIM];
__device__ __align__(16) float g_uwt[(size_t)NEXP * HID * DIM];
__device__ __align__(16) float g_dwt[(size_t)NEXP * DIM * HID];
__device__ __align__(16) float g_sgwt[(size_t)SHID * DIM];
__device__ __align__(16) float g_suwt[(size_t)SHID * DIM];
__device__ __align__(16) float g_sdwt[(size_t)DIM * SHID];
// intermediates
__device__ __align__(16) float g_G[(size_t)NROWS * HID];
__device__ __align__(16) float g_U[(size_t)NROWS * HID];
__device__ __align__(16) float g_H[(size_t)NROWS * HID];    // tf32-bit, permuted
__device__ __align__(16) float g_sG[(size_t)NTOK * SHID];
__device__ __align__(16) float g_sU[(size_t)NTOK * SHID];
__device__ __align__(16) float g_sH[(size_t)NTOK * SHID];   // tf32-bit, permuted
__device__ __align__(16) float g_Y[(size_t)NROWS * DIM];

// ---------------- helpers ---------------------------------------------------
__device__ __forceinline__ uint32_t f2tf(float x) {
    uint32_t r; asm("cvt.rna.tf32.f32 %0, %1;" : "=r"(r) : "f"(x)); return r;
}
__device__ __forceinline__ uint32_t s2u(const void* p) {
    uint32_t r;
    asm("{.reg .u64 t; cvta.to.shared.u64 t, %1; cvt.u32.u64 %0, t;}" : "=r"(r) : "l"(p));
    return r;
}
__device__ __forceinline__ void cpa16(uint32_t daddr, const float* src, bool pred) {
    int sz = pred ? 16 : 0;
    asm volatile("cp.async.cg.shared.global [%0], [%1], 16, %2;\n"
                 :: "r"(daddr), "l"(src), "r"(sz));
}
__device__ __forceinline__ void cp_commit() {
    asm volatile("cp.async.commit_group;\n" ::);
}
template<int N> __device__ __forceinline__ void cp_wait() {
    asm volatile("cp.async.wait_group %0;\n" :: "n"(N));
}
__device__ __forceinline__ void mma8(float* c, const uint32_t* a, const uint32_t* b) {
    asm volatile(
        "mma.sync.aligned.m16n8k8.row.col.f32.tf32.tf32.f32 "
        "{%0,%1,%2,%3}, {%4,%5,%6,%7}, {%8,%9}, {%0,%1,%2,%3};"
        : "+f"(c[0]), "+f"(c[1]), "+f"(c[2]), "+f"(c[3])
        : "r"(a[0]), "r"(a[1]), "r"(a[2]), "r"(a[3]), "r"(b[0]), "r"(b[1]));
}
__device__ __forceinline__ float silu_mul(float g, float u) {
    return g / (1.f + __expf(-g)) * u;
}

// 128x128 block tile, 8 warps (4m x 2n), warp tile 32x64, k-step 32.
// Data in smem is tf32 bits, k-permuted per 8-group [0,4,1,5,2,6,3,7]
// so fragment pairs (k, k+4) are contiguous -> LDS.64.
__device__ __forceinline__ void compute_k32p(
    const float* __restrict__ As, const float* __restrict__ Bs,
    int wm, int wn, int g, int tig, float acc[2][8][4]) {
#pragma unroll
    for (int ks = 0; ks < 4; ks++) {
        int kp = ks * 8 + 2 * tig;
        uint32_t af[2][4];
#pragma unroll
        for (int mt = 0; mt < 2; mt++) {
            int r = wm + mt * 16 + g;
            uint2 lo = *reinterpret_cast<const uint2*>(As + r * 36 + kp);
            uint2 hi = *reinterpret_cast<const uint2*>(As + (r + 8) * 36 + kp);
            af[mt][0] = lo.x; af[mt][1] = hi.x; af[mt][2] = lo.y; af[mt][3] = hi.y;
        }
#pragma unroll
        for (int nt = 0; nt < 8; nt++) {
            int cn = wn + nt * 8 + g;
            uint2 bv = *reinterpret_cast<const uint2*>(Bs + cn * 36 + kp);
            uint32_t bf[2] = { bv.x, bv.y };
#pragma unroll
            for (int mt = 0; mt < 2; mt++) mma8(acc[mt][nt], af[mt], bf);
        }
    }
}

// stage layout (floats): A0 [0,4608) A1 [4608,9216) B0 [9216,13824) B1 [13824,18432)
#define STAGE_F 4608
#define SMEM_PIPE_BYTES (4 * STAGE_F * 4)

__device__ __forceinline__ void issue_stage(
    uint32_t sAbase, uint32_t sBbase, int stage,
    const int* rr, const int* qq,
    const float* const* aP, const bool* av, const float* const* bP, int kb) {
    uint32_t so = (uint32_t)stage * STAGE_F * 4;
#pragma unroll
    for (int i = 0; i < 4; i++) {
        uint32_t o = (uint32_t)((rr[i] * 36 + qq[i] * 4) * 4);
        cpa16(sAbase + so + o, aP[i] + kb, av[i]);
        cpa16(sBbase + so + o, bP[i] + kb, true);
    }
    cp_commit();
}

#define PIPE_LOOP(NITER)                                                        \
    issue_stage(sA, sB, 0, rr, qq, aP, av, bP, 0);                              \
    for (int it = 0; it < (NITER); it++) {                                      \
        if (it + 1 < (NITER))                                                   \
            issue_stage(sA, sB, (it + 1) & 1, rr, qq, aP, av, bP, (it + 1) * 32);\
        if (it + 1 < (NITER)) cp_wait<1>(); else cp_wait<0>();                  \
        __syncthreads();                                                        \
        compute_k32p(sm + (it & 1) * STAGE_F, sm + 2 * STAGE_F + (it & 1) * STAGE_F, \
                     wm, wn, g, tig, acc);                                      \
        __syncthreads();                                                        \
    }

// ---------------- K-pre: convert + k-permute to tf32 bits -------------------
// dst position p within each 8-group holds src column: p even -> p/2, p odd -> 4+p/2
__global__ __launch_bounds__(256) void conv_kernel(
    const float* __restrict__ src, float* __restrict__ dst, size_t n4) {
    size_t q = (size_t)blockIdx.x * 256 + threadIdx.x;
    if (q >= n4) return;
    size_t e = q * 4;
    size_t base = e & ~(size_t)7;
    int off = (int)(e & 7);   // 0 or 4
    const float* s = src + base;
    float4 o;
#pragma unroll
    for (int m = 0; m < 4; m++) {
        int p = off + m;
        int k = (p & 1) ? 4 + (p >> 1) : (p >> 1);
        ((float*)&o)[m] = __uint_as_float(f2tf(s[k]));
    }
    *(float4*)(dst + e) = o;
}

// ---------------- K0: init counters ----------------------------------------
__global__ void init_kernel() {
    int t = threadIdx.x;
    if (t < NEXP) { g_counts[t] = 0; g_cursor[t] = 0; }
}

// ---------------- K1: router logits (fp32 SIMT, exact routing) -------------
__global__ __launch_bounds__(256) void router_kernel(
    const float* __restrict__ x, const float* __restrict__ rw,
    const float* __restrict__ rb) {
    __shared__ float xs[8 * DIM];
    int tok0 = blockIdx.x * 8;
    int t = threadIdx.x;
#pragma unroll
    for (int i = 0; i < 8; i++) {
        int s = t + i * 256;
        int r = s >> 8; int q = s & 255;
        *(float4*)(xs + r * DIM + q * 4) =
            *(const float4*)(x + (size_t)(tok0 + r) * DIM + q * 4);
    }
    __syncthreads();
    int tl = t >> 5, e = t & 31;
    float acc = rb[e];
    const float4* xv = (const float4*)(xs + tl * DIM);
    const float4* wv = (const float4*)(rw + (size_t)e * DIM);
#pragma unroll 4
    for (int q = 0; q < DIM / 4; q++) {
        float4 a = xv[q], b = wv[q];
        acc = fmaf(a.x, b.x, acc); acc = fmaf(a.y, b.y, acc);
        acc = fmaf(a.z, b.z, acc); acc = fmaf(a.w, b.w, acc);
    }
    g_logits[(size_t)(tok0 + tl) * NEXP + e] = acc;
}

// ---------------- K2: softmax + top4 + renormalize --------------------------
__global__ __launch_bounds__(256) void topk_kernel() {
    int warp = threadIdx.x >> 5;
    int lane = threadIdx.x & 31;
    int tok = blockIdx.x * 8 + warp;
    float l = g_logits[(size_t)tok * NEXP + lane];
    float m = l;
#pragma unroll
    for (int o = 16; o; o >>= 1) m = fmaxf(m, __shfl_xor_sync(~0u, m, o));
    float p = __expf(l - m);
    float s = p;
#pragma unroll
    for (int o = 16; o; o >>= 1) s += __shfl_xor_sync(~0u, s, o);
    float sc = p / s;

    float cs[TK]; int ci[TK];
    float cur = sc;
#pragma unroll
    for (int t = 0; t < TK; t++) {
        float v = cur; int vi = lane;
#pragma unroll
        for (int o = 16; o; o >>= 1) {
            float ov = __shfl_xor_sync(~0u, v, o);
            int   oi = __shfl_xor_sync(~0u, vi, o);
            if (ov > v || (ov == v && oi < vi)) { v = ov; vi = oi; }
        }
        cs[t] = v; ci[t] = vi;
        if (lane == vi) cur = -1.f;
    }
    float ssum = cs[0] + cs[1] + cs[2] + cs[3];
    float inv = 1.f / fmaxf(ssum, 1e-12f);
    if (lane < TK) {
        g_topk_idx[tok * TK + lane] = ci[lane];
        g_topk_sc [tok * TK + lane] = cs[lane] * inv;
        atomicAdd(&g_counts[ci[lane]], 1);
    }
}

// ---------------- K3: scan ---------------------------------------------------
__global__ void scan_kernel() {
    if (threadIdx.x == 0) {
        int acc = 0;
        g_offsets[0] = 0;
        for (int e = 0; e < NEXP; e++) { acc += g_counts[e]; g_offsets[e + 1] = acc; }
    }
    __syncthreads();
    if (threadIdx.x < NEXP) g_cursor[threadIdx.x] = g_offsets[threadIdx.x];
}

// ---------------- K4: scatter ------------------------------------------------
__global__ __launch_bounds__(256) void scatter_kernel() {
    int i = blockIdx.x * 256 + threadIdx.x;
    int e = g_topk_idx[i];
    int pos = atomicAdd(&g_cursor[e], 1);
    g_bucket_tok[pos] = i >> 2;
    g_bucket_sc [pos] = g_topk_sc[i];
    g_tok_pos[i] = pos;
}

// ---------------- K5: routed gate/up GEMM (pipelined tf32, gather-A) --------
__global__ __launch_bounds__(256, 2) void moe_gu_kernel(
    const float* __restrict__ gwp, const float* __restrict__ uwp) {
    int e = blockIdx.y;
    int off = g_offsets[e], cnt = g_offsets[e + 1] - off;
    int tile0 = blockIdx.x * 128;
    if (tile0 >= cnt) return;
    const float* W = (blockIdx.z == 0 ? gwp : uwp) + (size_t)e * HID * DIM;
    float* OUT = (blockIdx.z == 0 ? g_G : g_U);
    extern __shared__ float sm[];
    __shared__ int toks[128];
    int t = threadIdx.x;
    if (t < 128) { int m = tile0 + t; toks[t] = (m < cnt) ? g_bucket_tok[off + m] : -1; }
    __syncthreads();

    int rr[4], qq[4]; const float* aP[4]; const float* bP[4]; bool av[4];
#pragma unroll
    for (int i = 0; i < 4; i++) {
        int s = t + i * 256; rr[i] = s >> 3; qq[i] = s & 7;
        int tok = toks[rr[i]];
        av[i] = tok >= 0;
        aP[i] = g_xt + (size_t)(av[i] ? tok : 0) * DIM + qq[i] * 4;
        bP[i] = W + (size_t)rr[i] * DIM + qq[i] * 4;
    }
    uint32_t sA = s2u(sm), sB = s2u(sm + 2 * STAGE_F);
    int lane = t & 31, wid = t >> 5;
    int wm = (wid & 3) * 32, wn = (wid >> 2) * 64, g = lane >> 2, tig = lane & 3;
    float acc[2][8][4] = {};

    PIPE_LOOP(DIM / 32)

#pragma unroll
    for (int mt = 0; mt < 2; mt++) {
        int rA = tile0 + wm + mt * 16 + g;
#pragma unroll
        for (int nt = 0; nt < 8; nt++) {
            int col = wn + nt * 8 + 2 * tig;
            if (rA < cnt)
                *(float2*)(OUT + (size_t)(off + rA) * HID + col) =
                    make_float2(acc[mt][nt][0], acc[mt][nt][1]);
            if (rA + 8 < cnt)
                *(float2*)(OUT + (size_t)(off + rA + 8) * HID + col) =
                    make_float2(acc[mt][nt][2], acc[mt][nt][3]);
        }
    }
}

// ---------------- K6: SiLU(g)*u -> tf32 bits, k-permuted ---------------------
__global__ __launch_bounds__(256) void act_kernel(int which) {
    size_t q = (size_t)blockIdx.x * 256 + threadIdx.x;
    const float4* G = which ? (const float4*)g_sG : (const float4*)g_G;
    const float4* U = which ? (const float4*)g_sU : (const float4*)g_U;
    float* H = which ? g_sH : g_H;
    float4 gv = G[q], uv = U[q];
    float r0 = silu_mul(gv.x, uv.x);
    float r1 = silu_mul(gv.y, uv.y);
    float r2 = silu_mul(gv.z, uv.z);
    float r3 = silu_mul(gv.w, uv.w);
    size_t e = q * 4;
    size_t base = e & ~(size_t)7;
    int odd = (int)((e >> 2) & 1);
    // col k = base + 4*odd + m  ->  dst pos = base + 2*m + odd
    H[base + odd + 0] = __uint_as_float(f2tf(r0));
    H[base + odd + 2] = __uint_as_float(f2tf(r1));
    H[base + odd + 4] = __uint_as_float(f2tf(r2));
    H[base + odd + 6] = __uint_as_float(f2tf(r3));
}

// ---------------- K7: routed down GEMM (pipelined tf32), scaled -> Y --------
__global__ __launch_bounds__(256, 2) void moe_down_kernel(const float* __restrict__ dwp) {
    int e = blockIdx.z;
    int off = g_offsets[e], cnt = g_offsets[e + 1] - off;
    int tile0 = blockIdx.x * 128;
    if (tile0 >= cnt) return;
    int nb = blockIdx.y * 128;
    const float* W = dwp + (size_t)e * DIM * HID;
    extern __shared__ float sm[];
    __shared__ float scs[128];
    int t = threadIdx.x;
    if (t < 128) { int m = tile0 + t; scs[t] = (m < cnt) ? g_bucket_sc[off + m] : 0.f; }

    int rr[4], qq[4]; const float* aP[4]; const float* bP[4]; bool av[4];
#pragma unroll
    for (int i = 0; i < 4; i++) {
        int s = t + i * 256; rr[i] = s >> 3; qq[i] = s & 7;
        int m = tile0 + rr[i];
        av[i] = m < cnt;
        aP[i] = g_H + (size_t)(off + (av[i] ? m : 0)) * HID + qq[i] * 4;
        bP[i] = W + (size_t)(nb + rr[i]) * HID + qq[i] * 4;
    }
    uint32_t sA = s2u(sm), sB = s2u(sm + 2 * STAGE_F);
    int lane = t & 31, wid = t >> 5;
    int wm = (wid & 3) * 32, wn = (wid >> 2) * 64, g = lane >> 2, tig = lane & 3;
    float acc[2][8][4] = {};

    PIPE_LOOP(HID / 32)

#pragma unroll
    for (int mt = 0; mt < 2; mt++) {
        int rL = wm + mt * 16 + g;
        int rA = tile0 + rL;
#pragma unroll
        for (int nt = 0; nt < 8; nt++) {
            int col = nb + wn + nt * 8 + 2 * tig;
            if (rA < cnt) {
                float s = scs[rL];
                *(float2*)(g_Y + (size_t)(off + rA) * DIM + col) =
                    make_float2(acc[mt][nt][0] * s, acc[mt][nt][1] * s);
            }
            if (rA + 8 < cnt) {
                float s = scs[rL + 8];
                *(float2*)(g_Y + (size_t)(off + rA + 8) * DIM + col) =
                    make_float2(acc[mt][nt][2] * s, acc[mt][nt][3] * s);
            }
        }
    }
}

// ---------------- K8: shared gate/up GEMM (pipelined tf32) -------------------
__global__ __launch_bounds__(256, 2) void shared_gu_kernel(
    const float* __restrict__ sgwp, const float* __restrict__ suwp) {
    int tile0 = blockIdx.x * 128;
    int nb = blockIdx.y * 128;
    const float* W = (blockIdx.z == 0 ? sgwp : suwp);
    float* OUT = (blockIdx.z == 0 ? g_sG : g_sU);
    extern __shared__ float sm[];
    int t = threadIdx.x;

    int rr[4], qq[4]; const float* aP[4]; const float* bP[4]; bool av[4];
#pragma unroll
    for (int i = 0; i < 4; i++) {
        int s = t + i * 256; rr[i] = s >> 3; qq[i] = s & 7;
        av[i] = true;
        aP[i] = g_xt + (size_t)(tile0 + rr[i]) * DIM + qq[i] * 4;
        bP[i] = W + (size_t)(nb + rr[i]) * DIM + qq[i] * 4;
    }
    uint32_t sA = s2u(sm), sB = s2u(sm + 2 * STAGE_F);
    int lane = t & 31, wid = t >> 5;
    int wm = (wid & 3) * 32, wn = (wid >> 2) * 64, g = lane >> 2, tig = lane & 3;
    float acc[2][8][4] = {};

    PIPE_LOOP(DIM / 32)

#pragma unroll
    for (int mt = 0; mt < 2; mt++) {
        int rA = tile0 + wm + mt * 16 + g;
#pragma unroll
        for (int nt = 0; nt < 8; nt++) {
            int col = nb + wn + nt * 8 + 2 * tig;
            *(float2*)(OUT + (size_t)rA * SHID + col) = make_float2(acc[mt][nt][0], acc[mt][nt][1]);
            *(float2*)(OUT + (size_t)(rA + 8) * SHID + col) = make_float2(acc[mt][nt][2], acc[mt][nt][3]);
        }
    }
}

// ---------------- K9: final GEMM + Y gather (pipelined tf32) -----------------
__global__ __launch_bounds__(256, 2) void final_kernel(
    const float* __restrict__ sdwp, float* __restrict__ out) {
    int tile0 = blockIdx.x * 128;
    int nb = blockIdx.y * 128;
    extern __shared__ float sm[];
    int t = threadIdx.x;

    int rr[4], qq[4]; const float* aP[4]; const float* bP[4]; bool av[4];
#pragma unroll
    for (int i = 0; i < 4; i++) {
        int s = t + i * 256; rr[i] = s >> 3; qq[i] = s & 7;
        av[i] = true;
        aP[i] = g_sH + (size_t)(tile0 + rr[i]) * SHID + qq[i] * 4;
        bP[i] = sdwp + (size_t)(nb + rr[i]) * SHID + qq[i] * 4;
    }
    uint32_t sA = s2u(sm), sB = s2u(sm + 2 * STAGE_F);
    int lane = t & 31, wid = t >> 5;
    int wm = (wid & 3) * 32, wn = (wid >> 2) * 64, g = lane >> 2, tig = lane & 3;
    float acc[2][8][4] = {};

    PIPE_LOOP(SHID / 32)

#pragma unroll
    for (int mt = 0; mt < 2; mt++) {
        int r0 = tile0 + wm + mt * 16 + g;
        int4 tpa = *(const int4*)(g_tok_pos + r0 * TK);
        int4 tpb = *(const int4*)(g_tok_pos + (r0 + 8) * TK);
#pragma unroll
        for (int nt = 0; nt < 8; nt++) {
            int col = nb + wn + nt * 8 + 2 * tig;
            float2 y0 = *(const float2*)(g_Y + (size_t)tpa.x * DIM + col);
            float2 y1 = *(const float2*)(g_Y + (size_t)tpa.y * DIM + col);
            float2 y2 = *(const float2*)(g_Y + (size_t)tpa.z * DIM + col);
            float2 y3 = *(const float2*)(g_Y + (size_t)tpa.w * DIM + col);
            float2 ra;
            ra.x = acc[mt][nt][0] + y0.x + y1.x + y2.x + y3.x;
            ra.y = acc[mt][nt][1] + y0.y + y1.y + y2.y + y3.y;
            *(float2*)(out + (size_t)r0 * DIM + col) = ra;
            float2 z0 = *(const float2*)(g_Y + (size_t)tpb.x * DIM + col);
            float2 z1 = *(const float2*)(g_Y + (size_t)tpb.y * DIM + col);
            float2 z2 = *(const float2*)(g_Y + (size_t)tpb.z * DIM + col);
            float2 z3 = *(const float2*)(g_Y + (size_t)tpb.w * DIM + col);
            float2 rb;
            rb.x = acc[mt][nt][2] + z0.x + z1.x + z2.x + z3.x;
            rb.y = acc[mt][nt][3] + z0.y + z1.y + z2.y + z3.y;
            *(float2*)(out + (size_t)(r0 + 8) * DIM + col) = rb;
        }
    }
}

// ---------------- launch ------------------------------------------------------
static float* dptr(const void* sym) {
    void* p = nullptr; cudaGetSymbolAddress(&p, sym); return (float*)p;
}

extern "C" void kernel_launch(void* const* d_in, const int* in_sizes, int n_in,
                              void* d_out, int out_size) {
    const float* x   = (const float*)d_in[0];
    const float* rw  = (const float*)d_in[1];
    const float* rb  = (const float*)d_in[2];
    const float* gw  = (const float*)d_in[3];
    const float* uw  = (const float*)d_in[4];
    const float* dw  = (const float*)d_in[5];
    const float* sgw = (const float*)d_in[6];
    const float* suw = (const float*)d_in[7];
    const float* sdw = (const float*)d_in[8];
    float* out = (float*)d_out;

    static float *p_xt = nullptr, *p_gwt, *p_uwt, *p_dwt, *p_sgwt, *p_suwt, *p_sdwt;
    if (!p_xt) {
        cudaGetSymbolAddress((void**)&p_xt,   g_xt);
        cudaGetSymbolAddress((void**)&p_gwt,  g_gwt);
        cudaGetSymbolAddress((void**)&p_uwt,  g_uwt);
        cudaGetSymbolAddress((void**)&p_dwt,  g_dwt);
        cudaGetSymbolAddress((void**)&p_sgwt, g_sgwt);
        cudaGetSymbolAddress((void**)&p_suwt, g_suwt);
        cudaGetSymbolAddress((void**)&p_sdwt, g_sdwt);
    }

    cudaFuncSetAttribute(moe_gu_kernel,    cudaFuncAttributeMaxDynamicSharedMemorySize, SMEM_PIPE_BYTES);
    cudaFuncSetAttribute(moe_down_kernel,  cudaFuncAttributeMaxDynamicSharedMemorySize, SMEM_PIPE_BYTES);
    cudaFuncSetAttribute(shared_gu_kernel, cudaFuncAttributeMaxDynamicSharedMemorySize, SMEM_PIPE_BYTES);
    cudaFuncSetAttribute(final_kernel,     cudaFuncAttributeMaxDynamicSharedMemorySize, SMEM_PIPE_BYTES);

    // pre-convert everything to tf32 bits, k-permuted
    size_t nx = (size_t)NTOK * DIM / 4;
    conv_kernel<<<(unsigned)((nx + 255) / 256), 256>>>(x, p_xt, nx);
    size_t ng = (size_t)NEXP * HID * DIM / 4;
    conv_kernel<<<(unsigned)((ng + 255) / 256), 256>>>(gw, p_gwt, ng);
    conv_kernel<<<(unsigned)((ng + 255) / 256), 256>>>(uw, p_uwt, ng);
    conv_kernel<<<(unsigned)((ng + 255) / 256), 256>>>(dw, p_dwt, ng);
    size_t ns = (size_t)SHID * DIM / 4;
    conv_kernel<<<(unsigned)((ns + 255) / 256), 256>>>(sgw, p_sgwt, ns);
    conv_kernel<<<(unsigned)((ns + 255) / 256), 256>>>(suw, p_suwt, ns);
    conv_kernel<<<(unsigned)((ns + 255) / 256), 256>>>(sdw, p_sdwt, ns);

    init_kernel<<<1, 32>>>();
    router_kernel<<<NTOK / 8, 256>>>(x, rw, rb);
    topk_kernel<<<NTOK / 8, 256>>>();
    scan_kernel<<<1, 32>>>();
    scatter_kernel<<<NROWS / 256, 256>>>();
    moe_gu_kernel<<<dim3(64, NEXP, 2), 256, SMEM_PIPE_BYTES>>>(p_gwt, p_uwt);
    act_kernel<<<(NROWS * HID) / 4 / 256, 256>>>(0);
    moe_down_kernel<<<dim3(64, 8, NEXP), 256, SMEM_PIPE_BYTES>>>(p_dwt);
    shared_gu_kernel<<<dim3(64, 4, 2), 256, SMEM_PIPE_BYTES>>>(p_sgwt, p_suwt);
    act_kernel<<<((size_t)NTOK * SHID) / 4 / 256, 256>>>(1);
    final_kernel<<<dim3(64, 8), 256, SMEM_PIPE_BYTES>>>(p_sdwt, out);
}

// round 6
// speedup vs baseline: 1.5420x; 1.5420x over previous
#include <cuda_runtime.h>
#include <cuda_fp16.h>
#include <math.h>
#include <stdint.h>

#define NTOK 8192
#define DIM  1024
#define NEXP 32
#define HID  128
#define TK   4
#define SHID 512
#define NROWS (NTOK*TK)

// ---------------- scratch (device globals; no allocations) ----------------
__device__ __align__(16) float g_logits[NTOK * NEXP];
__device__ __align__(16) int   g_topk_idx[NROWS];
__device__ __align__(16) float g_topk_sc[NROWS];
__device__ __align__(16) int   g_counts[NEXP];
__device__ __align__(16) int   g_offsets[NEXP + 1];
__device__ __align__(16) int   g_cursor[NEXP];
__device__ __align__(16) int   g_bucket_tok[NROWS];
__device__ __align__(16) float g_bucket_sc[NROWS];
__device__ __align__(16) int   g_tok_pos[NROWS];
// fp16 copies (pre-convert pass)
__device__ __align__(16) __half g_xh[(size_t)NTOK * DIM];
__device__ __align__(16) __half g_gwh[(size_t)NEXP * HID * DIM];
__device__ __align__(16) __half g_uwh[(size_t)NEXP * HID * DIM];
__device__ __align__(16) __half g_dwh[(size_t)NEXP * DIM * HID];
__device__ __align__(16) __half g_sgwh[(size_t)SHID * DIM];
__device__ __align__(16) __half g_suwh[(size_t)SHID * DIM];
__device__ __align__(16) __half g_sdwh[(size_t)DIM * SHID];
// intermediates
__device__ __align__(16) float  g_G[(size_t)NROWS * HID];
__device__ __align__(16) float  g_U[(size_t)NROWS * HID];
__device__ __align__(16) __half g_Hh[(size_t)NROWS * HID];
__device__ __align__(16) float  g_sG[(size_t)NTOK * SHID];
__device__ __align__(16) float  g_sU[(size_t)NTOK * SHID];
__device__ __align__(16) __half g_sHh[(size_t)NTOK * SHID];
__device__ __align__(16) float  g_Y[(size_t)NROWS * DIM];

// ---------------- helpers ---------------------------------------------------
__device__ __forceinline__ uint32_t s2u(const void* p) {
    uint32_t r;
    asm("{.reg .u64 t; cvta.to.shared.u64 t, %1; cvt.u32.u64 %0, t;}" : "=r"(r) : "l"(p));
    return r;
}
// SW128 swizzle on 128B rows, 16B granularity
__device__ __forceinline__ uint32_t swz(uint32_t b) { return b ^ ((b >> 3) & 0x70); }

__device__ __forceinline__ void cpa16h(uint32_t daddr, const __half* src, bool pred) {
    int sz = pred ? 16 : 0;
    asm volatile("cp.async.cg.shared.global [%0], [%1], 16, %2;\n"
                 :: "r"(daddr), "l"(src), "r"(sz));
}
__device__ __forceinline__ void cp_commit() {
    asm volatile("cp.async.commit_group;\n" ::);
}
template<int N> __device__ __forceinline__ void cp_wait() {
    asm volatile("cp.async.wait_group %0;\n" :: "n"(N));
}
__device__ __forceinline__ void mma16(float* c, const uint32_t* a, const uint32_t* b) {
    asm volatile(
        "mma.sync.aligned.m16n8k16.row.col.f32.f16.f16.f32 "
        "{%0,%1,%2,%3}, {%4,%5,%6,%7}, {%8,%9}, {%0,%1,%2,%3};"
        : "+f"(c[0]), "+f"(c[1]), "+f"(c[2]), "+f"(c[3])
        : "r"(a[0]), "r"(a[1]), "r"(a[2]), "r"(a[3]), "r"(b[0]), "r"(b[1]));
}
__device__ __forceinline__ float silu_mul(float g, float u) {
    return g / (1.f + __expf(-g)) * u;
}

// Block tile 128x128, 8 warps (4m x 2n), warp tile 32x64, k-step 64 halves.
// Tiles in smem: 128 rows x 64 fp16 (128B rows), SW128-swizzled.
__device__ __forceinline__ void compute_k64h(
    uint32_t sAt, uint32_t sBt, int wm, int wn, int lane, float acc[2][8][4]) {
    int ar = lane & 15;            // A row within m16 tile
    int ac = lane >> 4;            // A chunk parity (k lo/hi 8)
    int br = (lane & 7) + ((lane >> 4) & 1) * 8;  // B row select
    int bc = (lane >> 3) & 1;      // B chunk parity
#pragma unroll
    for (int ks = 0; ks < 4; ks++) {
        uint32_t af[2][4];
#pragma unroll
        for (int mt = 0; mt < 2; mt++) {
            uint32_t ad = sAt + swz((uint32_t)((wm + mt * 16 + ar) * 128 + (ks * 2 + ac) * 16));
            asm volatile("ldmatrix.sync.aligned.m8n8.x4.shared.b16 {%0,%1,%2,%3}, [%4];"
                : "=r"(af[mt][0]), "=r"(af[mt][1]), "=r"(af[mt][2]), "=r"(af[mt][3]) : "r"(ad));
        }
        uint32_t bf[8][2];
#pragma unroll
        for (int j = 0; j < 4; j++) {
            uint32_t bd = sBt + swz((uint32_t)((wn + 16 * j + br) * 128 + (ks * 2 + bc) * 16));
            uint32_t r0, r1, r2, r3;
            asm volatile("ldmatrix.sync.aligned.m8n8.x4.shared.b16 {%0,%1,%2,%3}, [%4];"
                : "=r"(r0), "=r"(r1), "=r"(r2), "=r"(r3) : "r"(bd));
            bf[2*j][0] = r0; bf[2*j][1] = r1; bf[2*j+1][0] = r2; bf[2*j+1][1] = r3;
        }
#pragma unroll
        for (int mt = 0; mt < 2; mt++)
#pragma unroll
            for (int nt = 0; nt < 8; nt++) mma16(acc[mt][nt], af[mt], bf[nt]);
    }
}

#define TILE_BYTES 16384u
#define SMEM_H (4 * TILE_BYTES)   // A0 A1 B0 B1

__device__ __forceinline__ void issue_h(
    uint32_t sA, uint32_t sB, int stage,
    const int* rw, const int* cw,
    const __half* const* aP, const bool* av, const __half* const* bP, int kb) {
    uint32_t so = (uint32_t)stage * TILE_BYTES;
#pragma unroll
    for (int i = 0; i < 4; i++) {
        uint32_t o = swz((uint32_t)(rw[i] * 128 + cw[i] * 16));
        cpa16h(sA + so + o, aP[i] + kb, av[i]);
        cpa16h(sB + so + o, bP[i] + kb, true);
    }
    cp_commit();
}

#define PIPE_LOOP_H(NITER)                                                      \
    issue_h(sA, sB, 0, rw, cw, aP, av, bP, 0);                                  \
    for (int it = 0; it < (NITER); it++) {                                      \
        if (it + 1 < (NITER)) issue_h(sA, sB, (it + 1) & 1, rw, cw, aP, av, bP, (it + 1) * 64); \
        if (it + 1 < (NITER)) cp_wait<1>(); else cp_wait<0>();                  \
        __syncthreads();                                                        \
        compute_k64h(sA + (it & 1) * TILE_BYTES, sB + (it & 1) * TILE_BYTES,    \
                     wm, wn, lane, acc);                                        \
        __syncthreads();                                                        \
    }

// ---------------- K-pre: fp32 -> fp16 (8 elements per thread) ---------------
__global__ __launch_bounds__(256) void convh_kernel(
    const float* __restrict__ src, __half* __restrict__ dst, size_t n8) {
    size_t q = (size_t)blockIdx.x * 256 + threadIdx.x;
    if (q >= n8) return;
    const float4* s = (const float4*)(src + q * 8);
    float4 a = s[0], b = s[1];
    __half2 h[4];
    h[0] = __floats2half2_rn(a.x, a.y);
    h[1] = __floats2half2_rn(a.z, a.w);
    h[2] = __floats2half2_rn(b.x, b.y);
    h[3] = __floats2half2_rn(b.z, b.w);
    *(uint4*)(dst + q * 8) = *(uint4*)h;
}

// ---------------- K0: init counters ----------------------------------------
__global__ void init_kernel() {
    int t = threadIdx.x;
    if (t < NEXP) { g_counts[t] = 0; g_cursor[t] = 0; }
}

// ---------------- K1: router logits (fp32 SIMT, exact routing) -------------
__global__ __launch_bounds__(256) void router_kernel(
    const float* __restrict__ x, const float* __restrict__ rw,
    const float* __restrict__ rb) {
    __shared__ float xs[8 * DIM];
    int tok0 = blockIdx.x * 8;
    int t = threadIdx.x;
#pragma unroll
    for (int i = 0; i < 8; i++) {
        int s = t + i * 256;
        int r = s >> 8; int q = s & 255;
        *(float4*)(xs + r * DIM + q * 4) =
            *(const float4*)(x + (size_t)(tok0 + r) * DIM + q * 4);
    }
    __syncthreads();
    int tl = t >> 5, e = t & 31;
    float acc = rb[e];
    const float4* xv = (const float4*)(xs + tl * DIM);
    const float4* wv = (const float4*)(rw + (size_t)e * DIM);
#pragma unroll 4
    for (int q = 0; q < DIM / 4; q++) {
        float4 a = xv[q], b = wv[q];
        acc = fmaf(a.x, b.x, acc); acc = fmaf(a.y, b.y, acc);
        acc = fmaf(a.z, b.z, acc); acc = fmaf(a.w, b.w, acc);
    }
    g_logits[(size_t)(tok0 + tl) * NEXP + e] = acc;
}

// ---------------- K2: softmax + top4 + renormalize --------------------------
__global__ __launch_bounds__(256) void topk_kernel() {
    int warp = threadIdx.x >> 5;
    int lane = threadIdx.x & 31;
    int tok = blockIdx.x * 8 + warp;
    float l = g_logits[(size_t)tok * NEXP + lane];
    float m = l;
#pragma unroll
    for (int o = 16; o; o >>= 1) m = fmaxf(m, __shfl_xor_sync(~0u, m, o));
    float p = __expf(l - m);
    float s = p;
#pragma unroll
    for (int o = 16; o; o >>= 1) s += __shfl_xor_sync(~0u, s, o);
    float sc = p / s;

    float cs[TK]; int ci[TK];
    float cur = sc;
#pragma unroll
    for (int t = 0; t < TK; t++) {
        float v = cur; int vi = lane;
#pragma unroll
        for (int o = 16; o; o >>= 1) {
            float ov = __shfl_xor_sync(~0u, v, o);
            int   oi = __shfl_xor_sync(~0u, vi, o);
            if (ov > v || (ov == v && oi < vi)) { v = ov; vi = oi; }
        }
        cs[t] = v; ci[t] = vi;
        if (lane == vi) cur = -1.f;
    }
    float ssum = cs[0] + cs[1] + cs[2] + cs[3];
    float inv = 1.f / fmaxf(ssum, 1e-12f);
    if (lane < TK) {
        g_topk_idx[tok * TK + lane] = ci[lane];
        g_topk_sc [tok * TK + lane] = cs[lane] * inv;
        atomicAdd(&g_counts[ci[lane]], 1);
    }
}

// ---------------- K3: scan ---------------------------------------------------
__global__ void scan_kernel() {
    if (threadIdx.x == 0) {
        int acc = 0;
        g_offsets[0] = 0;
        for (int e = 0; e < NEXP; e++) { acc += g_counts[e]; g_offsets[e + 1] = acc; }
    }
    __syncthreads();
    if (threadIdx.x < NEXP) g_cursor[threadIdx.x] = g_offsets[threadIdx.x];
}

// ---------------- K4: scatter ------------------------------------------------
__global__ __launch_bounds__(256) void scatter_kernel() {
    int i = blockIdx.x * 256 + threadIdx.x;
    int e = g_topk_idx[i];
    int pos = atomicAdd(&g_cursor[e], 1);
    g_bucket_tok[pos] = i >> 2;
    g_bucket_sc [pos] = g_topk_sc[i];
    g_tok_pos[i] = pos;
}

// ---------------- K5: routed gate/up GEMM (fp16 MMA, gather-A) --------------
__global__ __launch_bounds__(256, 2) void moe_gu_kernel(
    const __half* __restrict__ gwp, const __half* __restrict__ uwp) {
    int e = blockIdx.y;
    int off = g_offsets[e], cnt = g_offsets[e + 1] - off;
    int tile0 = blockIdx.x * 128;
    if (tile0 >= cnt) return;
    const __half* W = (blockIdx.z == 0 ? gwp : uwp) + (size_t)e * HID * DIM;
    float* OUT = (blockIdx.z == 0 ? g_G : g_U);
    extern __shared__ __half smh[];
    uint32_t sA = s2u(smh), sB = sA + 2 * TILE_BYTES;
    __shared__ int toks[128];
    int t = threadIdx.x;
    if (t < 128) { int m = tile0 + t; toks[t] = (m < cnt) ? g_bucket_tok[off + m] : -1; }
    __syncthreads();

    int rw[4], cw[4]; const __half* aP[4]; const __half* bP[4]; bool av[4];
#pragma unroll
    for (int i = 0; i < 4; i++) {
        int c = t + i * 256; rw[i] = c >> 3; cw[i] = c & 7;
        int tok = toks[rw[i]];
        av[i] = tok >= 0;
        aP[i] = g_xh + (size_t)(av[i] ? tok : 0) * DIM + cw[i] * 8;
        bP[i] = W + (size_t)rw[i] * DIM + cw[i] * 8;
    }
    int lane = t & 31, wid = t >> 5;
    int wm = (wid & 3) * 32, wn = (wid >> 2) * 64, g = lane >> 2, tig = lane & 3;
    float acc[2][8][4] = {};

    PIPE_LOOP_H(DIM / 64)

#pragma unroll
    for (int mt = 0; mt < 2; mt++) {
        int rA = tile0 + wm + mt * 16 + g;
#pragma unroll
        for (int nt = 0; nt < 8; nt++) {
            int col = wn + nt * 8 + 2 * tig;
            if (rA < cnt)
                *(float2*)(OUT + (size_t)(off + rA) * HID + col) =
                    make_float2(acc[mt][nt][0], acc[mt][nt][1]);
            if (rA + 8 < cnt)
                *(float2*)(OUT + (size_t)(off + rA + 8) * HID + col) =
                    make_float2(acc[mt][nt][2], acc[mt][nt][3]);
        }
    }
}

// ---------------- K6: SiLU(g)*u -> fp16 --------------------------------------
__global__ __launch_bounds__(256) void acth_kernel(int which) {
    size_t q = (size_t)blockIdx.x * 256 + threadIdx.x;
    const float4* G = which ? (const float4*)g_sG : (const float4*)g_G;
    const float4* U = which ? (const float4*)g_sU : (const float4*)g_U;
    __half* H = which ? g_sHh : g_Hh;
    float4 g0 = G[q * 2], g1 = G[q * 2 + 1];
    float4 u0 = U[q * 2], u1 = U[q * 2 + 1];
    __half2 h[4];
    h[0] = __floats2half2_rn(silu_mul(g0.x, u0.x), silu_mul(g0.y, u0.y));
    h[1] = __floats2half2_rn(silu_mul(g0.z, u0.z), silu_mul(g0.w, u0.w));
    h[2] = __floats2half2_rn(silu_mul(g1.x, u1.x), silu_mul(g1.y, u1.y));
    h[3] = __floats2half2_rn(silu_mul(g1.z, u1.z), silu_mul(g1.w, u1.w));
    *(uint4*)(H + q * 8) = *(uint4*)h;
}

// ---------------- K7: routed down GEMM (fp16 MMA), scaled -> Y ---------------
__global__ __launch_bounds__(256, 2) void moe_down_kernel(const __half* __restrict__ dwp) {
    int e = blockIdx.z;
    int off = g_offsets[e], cnt = g_offsets[e + 1] - off;
    int tile0 = blockIdx.x * 128;
    if (tile0 >= cnt) return;
    int nb = blockIdx.y * 128;
    const __half* W = dwp + (size_t)e * DIM * HID;
    extern __shared__ __half smh[];
    uint32_t sA = s2u(smh), sB = sA + 2 * TILE_BYTES;
    __shared__ float scs[128];
    int t = threadIdx.x;
    if (t < 128) { int m = tile0 + t; scs[t] = (m < cnt) ? g_bucket_sc[off + m] : 0.f; }

    int rw[4], cw[4]; const __half* aP[4]; const __half* bP[4]; bool av[4];
#pragma unroll
    for (int i = 0; i < 4; i++) {
        int c = t + i * 256; rw[i] = c >> 3; cw[i] = c & 7;
        int m = tile0 + rw[i];
        av[i] = m < cnt;
        aP[i] = g_Hh + (size_t)(off + (av[i] ? m : 0)) * HID + cw[i] * 8;
        bP[i] = W + (size_t)(nb + rw[i]) * HID + cw[i] * 8;
    }
    int lane = t & 31, wid = t >> 5;
    int wm = (wid & 3) * 32, wn = (wid >> 2) * 64, g = lane >> 2, tig = lane & 3;
    float acc[2][8][4] = {};

    PIPE_LOOP_H(HID / 64)

#pragma unroll
    for (int mt = 0; mt < 2; mt++) {
        int rL = wm + mt * 16 + g;
        int rA = tile0 + rL;
#pragma unroll
        for (int nt = 0; nt < 8; nt++) {
            int col = nb + wn + nt * 8 + 2 * tig;
            if (rA < cnt) {
                float s = scs[rL];
                *(float2*)(g_Y + (size_t)(off + rA) * DIM + col) =
                    make_float2(acc[mt][nt][0] * s, acc[mt][nt][1] * s);
            }
            if (rA + 8 < cnt) {
                float s = scs[rL + 8];
                *(float2*)(g_Y + (size_t)(off + rA + 8) * DIM + col) =
                    make_float2(acc[mt][nt][2] * s, acc[mt][nt][3] * s);
            }
        }
    }
}

// ---------------- K8: shared gate/up GEMM (fp16 MMA) -------------------------
__global__ __launch_bounds__(256, 2) void shared_gu_kernel(
    const __half* __restrict__ sgwp, const __half* __restrict__ suwp) {
    int tile0 = blockIdx.x * 128;
    int nb = blockIdx.y * 128;
    const __half* W = (blockIdx.z == 0 ? sgwp : suwp);
    float* OUT = (blockIdx.z == 0 ? g_sG : g_sU);
    extern __shared__ __half smh[];
    uint32_t sA = s2u(smh), sB = sA + 2 * TILE_BYTES;
    int t = threadIdx.x;

    int rw[4], cw[4]; const __half* aP[4]; const __half* bP[4]; bool av[4];
#pragma unroll
    for (int i = 0; i < 4; i++) {
        int c = t + i * 256; rw[i] = c >> 3; cw[i] = c & 7;
        av[i] = true;
        aP[i] = g_xh + (size_t)(tile0 + rw[i]) * DIM + cw[i] * 8;
        bP[i] = W + (size_t)(nb + rw[i]) * DIM + cw[i] * 8;
    }
    int lane = t & 31, wid = t >> 5;
    int wm = (wid & 3) * 32, wn = (wid >> 2) * 64, g = lane >> 2, tig = lane & 3;
    float acc[2][8][4] = {};

    PIPE_LOOP_H(DIM / 64)

#pragma unroll
    for (int mt = 0; mt < 2; mt++) {
        int rA = tile0 + wm + mt * 16 + g;
#pragma unroll
        for (int nt = 0; nt < 8; nt++) {
            int col = nb + wn + nt * 8 + 2 * tig;
            *(float2*)(OUT + (size_t)rA * SHID + col) = make_float2(acc[mt][nt][0], acc[mt][nt][1]);
            *(float2*)(OUT + (size_t)(rA + 8) * SHID + col) = make_float2(acc[mt][nt][2], acc[mt][nt][3]);
        }
    }
}

// ---------------- K9: final GEMM (fp16 MMA) + Y gather ------------------------
__global__ __launch_bounds__(256, 2) void final_kernel(
    const __half* __restrict__ sdwp, float* __restrict__ out) {
    int tile0 = blockIdx.x * 128;
    int nb = blockIdx.y * 128;
    extern __shared__ __half smh[];
    uint32_t sA = s2u(smh), sB = sA + 2 * TILE_BYTES;
    int t = threadIdx.x;

    int rw[4], cw[4]; const __half* aP[4]; const __half* bP[4]; bool av[4];
#pragma unroll
    for (int i = 0; i < 4; i++) {
        int c = t + i * 256; rw[i] = c >> 3; cw[i] = c & 7;
        av[i] = true;
        aP[i] = g_sHh + (size_t)(tile0 + rw[i]) * SHID + cw[i] * 8;
        bP[i] = sdwp + (size_t)(nb + rw[i]) * SHID + cw[i] * 8;
    }
    int lane = t & 31, wid = t >> 5;
    int wm = (wid & 3) * 32, wn = (wid >> 2) * 64, g = lane >> 2, tig = lane & 3;
    float acc[2][8][4] = {};

    PIPE_LOOP_H(SHID / 64)

#pragma unroll
    for (int mt = 0; mt < 2; mt++) {
        int r0 = tile0 + wm + mt * 16 + g;
        int4 tpa = *(const int4*)(g_tok_pos + r0 * TK);
        int4 tpb = *(const int4*)(g_tok_pos + (r0 + 8) * TK);
#pragma unroll
        for (int nt = 0; nt < 8; nt++) {
            int col = nb + wn + nt * 8 + 2 * tig;
            float2 y0 = *(const float2*)(g_Y + (size_t)tpa.x * DIM + col);
            float2 y1 = *(const float2*)(g_Y + (size_t)tpa.y * DIM + col);
            float2 y2 = *(const float2*)(g_Y + (size_t)tpa.z * DIM + col);
            float2 y3 = *(const float2*)(g_Y + (size_t)tpa.w * DIM + col);
            float2 ra;
            ra.x = acc[mt][nt][0] + y0.x + y1.x + y2.x + y3.x;
            ra.y = acc[mt][nt][1] + y0.y + y1.y + y2.y + y3.y;
            *(float2*)(out + (size_t)r0 * DIM + col) = ra;
            float2 z0 = *(const float2*)(g_Y + (size_t)tpb.x * DIM + col);
            float2 z1 = *(const float2*)(g_Y + (size_t)tpb.y * DIM + col);
            float2 z2 = *(const float2*)(g_Y + (size_t)tpb.z * DIM + col);
            float2 z3 = *(const float2*)(g_Y + (size_t)tpb.w * DIM + col);
            float2 rb;
            rb.x = acc[mt][nt][2] + z0.x + z1.x + z2.x + z3.x;
            rb.y = acc[mt][nt][3] + z0.y + z1.y + z2.y + z3.y;
            *(float2*)(out + (size_t)(r0 + 8) * DIM + col) = rb;
        }
    }
}

// ---------------- launch ------------------------------------------------------
extern "C" void kernel_launch(void* const* d_in, const int* in_sizes, int n_in,
                              void* d_out, int out_size) {
    const float* x   = (const float*)d_in[0];
    const float* rw  = (const float*)d_in[1];
    const float* rb  = (const float*)d_in[2];
    const float* gw  = (const float*)d_in[3];
    const float* uw  = (const float*)d_in[4];
    const float* dw  = (const float*)d_in[5];
    const float* sgw = (const float*)d_in[6];
    const float* suw = (const float*)d_in[7];
    const float* sdw = (const float*)d_in[8];
    float* out = (float*)d_out;

    static __half *p_xh = nullptr, *p_gwh, *p_uwh, *p_dwh, *p_sgwh, *p_suwh, *p_sdwh;
    if (!p_xh) {
        cudaGetSymbolAddress((void**)&p_xh,   g_xh);
        cudaGetSymbolAddress((void**)&p_gwh,  g_gwh);
        cudaGetSymbolAddress((void**)&p_uwh,  g_uwh);
        cudaGetSymbolAddress((void**)&p_dwh,  g_dwh);
        cudaGetSymbolAddress((void**)&p_sgwh, g_sgwh);
        cudaGetSymbolAddress((void**)&p_suwh, g_suwh);
        cudaGetSymbolAddress((void**)&p_sdwh, g_sdwh);
    }

    cudaFuncSetAttribute(moe_gu_kernel,    cudaFuncAttributeMaxDynamicSharedMemorySize, SMEM_H);
    cudaFuncSetAttribute(moe_down_kernel,  cudaFuncAttributeMaxDynamicSharedMemorySize, SMEM_H);
    cudaFuncSetAttribute(shared_gu_kernel, cudaFuncAttributeMaxDynamicSharedMemorySize, SMEM_H);
    cudaFuncSetAttribute(final_kernel,     cudaFuncAttributeMaxDynamicSharedMemorySize, SMEM_H);

    // pre-convert to fp16
    size_t nx = (size_t)NTOK * DIM / 8;
    convh_kernel<<<(unsigned)((nx + 255) / 256), 256>>>(x, p_xh, nx);
    size_t ng = (size_t)NEXP * HID * DIM / 8;
    convh_kernel<<<(unsigned)((ng + 255) / 256), 256>>>(gw, p_gwh, ng);
    convh_kernel<<<(unsigned)((ng + 255) / 256), 256>>>(uw, p_uwh, ng);
    convh_kernel<<<(unsigned)((ng + 255) / 256), 256>>>(dw, p_dwh, ng);
    size_t ns = (size_t)SHID * DIM / 8;
    convh_kernel<<<(unsigned)((ns + 255) / 256), 256>>>(sgw, p_sgwh, ns);
    convh_kernel<<<(unsigned)((ns + 255) / 256), 256>>>(suw, p_suwh, ns);
    convh_kernel<<<(unsigned)((ns + 255) / 256), 256>>>(sdw, p_sdwh, ns);

    init_kernel<<<1, 32>>>();
    router_kernel<<<NTOK / 8, 256>>>(x, rw, rb);
    topk_kernel<<<NTOK / 8, 256>>>();
    scan_kernel<<<1, 32>>>();
    scatter_kernel<<<NROWS / 256, 256>>>();
    moe_gu_kernel<<<dim3(64, NEXP, 2), 256, SMEM_H>>>(p_gwh, p_uwh);
    acth_kernel<<<(NROWS * HID) / 8 / 256, 256>>>(0);
    moe_down_kernel<<<dim3(64, 8, NEXP), 256, SMEM_H>>>(p_dwh);
    shared_gu_kernel<<<dim3(64, 4, 2), 256, SMEM_H>>>(p_sgwh, p_suwh);
    acth_kernel<<<((size_t)NTOK * SHID) / 8 / 256, 256>>>(1);
    final_kernel<<<dim3(64, 8), 256, SMEM_H>>>(p_sdwh, out);
}